// round 6
// baseline (speedup 1.0000x reference)
#include <cuda_runtime.h>
#include <math.h>

#define B_   32
#define T_   1024
#define IN_  64
#define RES_ 2048
#define HID_ 512
#define OUT_ 64
#define BT_  (B_ * T_)
#define NCTA_ 128

typedef unsigned long long ull;

// ---- packed fp32x2 helpers ----
__device__ __forceinline__ void ffma2(ull& d, ull a, ull b)
{
    asm("fma.rn.f32x2 %0, %1, %2, %0;" : "+l"(d) : "l"(a), "l"(b));
}
__device__ __forceinline__ ull splat2(float h)
{
    ull r;
    asm("mov.b64 %0, {%1, %1};" : "=l"(r) : "f"(h));
    return r;
}
__device__ __forceinline__ void unpack2(ull v, float& lo, float& hi)
{
    asm("mov.b64 {%0, %1}, %2;" : "=f"(lo), "=f"(hi) : "l"(v));
}

// ---- release/acquire flag ops (no membar, no CCTL) ----
__device__ __forceinline__ unsigned ld_acq(const unsigned* p)
{
    unsigned v;
    asm volatile("ld.acquire.gpu.global.u32 %0, [%1];" : "=r"(v) : "l"(p));
    return v;
}
__device__ __forceinline__ void st_rel(unsigned* p, unsigned v)
{
    asm volatile("st.release.gpu.global.u32 [%0], %1;" :: "l"(p), "r"(v) : "memory");
}
__device__ __forceinline__ void wait_flag(const unsigned* p, unsigned target)
{
    if ((int)(ld_acq(p) - target) >= 0) return;
    while ((int)(ld_acq(p) - target) < 0) __nanosleep(32);
}

// ---------------- scratch ----------------
__device__ float g_UT[(size_t)T_ * RES_ * B_];
__device__ float g_h0[RES_ * B_];
__device__ float g_h1[RES_ * B_];
__device__ float g_a1[(size_t)BT_ * HID_];
__device__ float g_a2[(size_t)BT_ * HID_];
__device__ unsigned g_flags[NCTA_];      // per-CTA published step count (monotonic)

// ---------------- U = x @ W_in^T -> UT[t][r][b] ----------------
__global__ void __launch_bounds__(256) u_kernel(const float* __restrict__ x,
                                                const float* __restrict__ Win,
                                                float* __restrict__ UT)
{
    __shared__ float xS[IN_][B_];
    __shared__ float wS[IN_][128];
    const int t   = blockIdx.y;
    const int R0  = blockIdx.x * 128;
    const int tid = threadIdx.x;

    {
        int b  = tid >> 3;
        int iq = (tid & 7) * 8;
        const float* src = x + (size_t)b * (T_ * IN_) + (size_t)t * IN_ + iq;
        float4 v0 = *(const float4*)(src);
        float4 v1 = *(const float4*)(src + 4);
        xS[iq + 0][b] = v0.x; xS[iq + 1][b] = v0.y; xS[iq + 2][b] = v0.z; xS[iq + 3][b] = v0.w;
        xS[iq + 4][b] = v1.x; xS[iq + 5][b] = v1.y; xS[iq + 6][b] = v1.z; xS[iq + 7][b] = v1.w;
    }
    {
        int r  = tid >> 1;
        int ih = (tid & 1) * 32;
        const float* src = Win + (size_t)(R0 + r) * IN_ + ih;
#pragma unroll
        for (int j = 0; j < 32; j += 4) {
            float4 v = *(const float4*)(src + j);
            wS[ih + j + 0][r] = v.x; wS[ih + j + 1][r] = v.y;
            wS[ih + j + 2][r] = v.z; wS[ih + j + 3][r] = v.w;
        }
    }
    __syncthreads();

    const int tx = tid & 7, ty = tid >> 3;
    const int b0 = tx * 4, r0 = ty * 4;
    float acc[4][4];
#pragma unroll
    for (int i = 0; i < 4; i++)
#pragma unroll
        for (int j = 0; j < 4; j++) acc[i][j] = 0.f;

#pragma unroll
    for (int i = 0; i < IN_; i++) {
        float4 xv = *(const float4*)&xS[i][b0];
        float4 wv = *(const float4*)&wS[i][r0];
        float xa[4] = {xv.x, xv.y, xv.z, xv.w};
        float wa[4] = {wv.x, wv.y, wv.z, wv.w};
#pragma unroll
        for (int ri = 0; ri < 4; ri++)
#pragma unroll
            for (int bi = 0; bi < 4; bi++)
                acc[ri][bi] = fmaf(wa[ri], xa[bi], acc[ri][bi]);
    }
    float* dst = UT + (size_t)t * (RES_ * B_);
#pragma unroll
    for (int ri = 0; ri < 4; ri++) {
        float4 v = make_float4(acc[ri][0], acc[ri][1], acc[ri][2], acc[ri][3]);
        *(float4*)(dst + (size_t)(R0 + r0 + ri) * B_ + b0) = v;
    }
}

// ---- 8-k FMA block: consumes hv[8], W from SMEM ----
__device__ __forceinline__ void fma_block8(ull acc2[8], const float* __restrict__ wS,
                                           int kbase, const float hv[8])
{
#pragma unroll
    for (int u = 0; u < 8; u++) {
        const ull* wr = (const ull*)&wS[(kbase + u) * 16];
        ulonglong2 p0 = *(const ulonglong2*)(wr + 0);
        ulonglong2 p1 = *(const ulonglong2*)(wr + 2);
        ulonglong2 p2 = *(const ulonglong2*)(wr + 4);
        ulonglong2 p3 = *(const ulonglong2*)(wr + 6);
        ull hh = splat2(hv[u]);
        ffma2(acc2[0], p0.x, hh);
        ffma2(acc2[1], p0.y, hh);
        ffma2(acc2[2], p1.x, hh);
        ffma2(acc2[3], p1.y, hh);
        ffma2(acc2[4], p2.x, hh);
        ffma2(acc2[5], p2.y, hh);
        ffma2(acc2[6], p3.x, hh);
        ffma2(acc2[7], p3.y, hh);
    }
}

// ---------------- persistent ESN scan: dataflow flags, no global barrier ----------------
// CTA bid owns h rows [16*bid, 16*bid+16). After step t it publishes
// flags[bid] = epoch + t + 1 (release). Consumers acquire-wait per 16-row chunk
// right before consuming it, interleaved with the ping-pong h prefetch.
__global__ void __launch_bounds__(512) scan_persistent_kernel(const float* __restrict__ Wh,
                                                              float* __restrict__ hA,
                                                              float* __restrict__ hB,
                                                              float* __restrict__ UT)
{
    extern __shared__ float dyn[];
    float* wS  = dyn;                 // wS[k*16 + n]
    float* red = dyn + RES_ * 16;     // red[(n*16 + w)*32 + b]

    const int tid  = threadIdx.x;
    const int w    = tid >> 5;
    const int lane = tid & 31;
    const int bid  = blockIdx.x;
    const int n0   = bid * 16;
    const int k0   = w * 128;
    const int cbase = w * 8;          // first producer-chunk this warp consumes

    // all flags are equal at launch start (each CTA published T_ steps last launch)
    const unsigned epoch = g_flags[bid];

    // one-time: cache W_hat slice transposed into SMEM
    {
        int n = tid >> 5;
        const float* row = Wh + (size_t)(n0 + n) * RES_;
#pragma unroll
        for (int j = 0; j < 16; j++) {
            int k = j * 128 + lane * 4;
            float4 v = *(const float4*)(row + k);
            wS[(k + 0) * 16 + n] = v.x;
            wS[(k + 1) * 16 + n] = v.y;
            wS[(k + 2) * 16 + n] = v.z;
            wS[(k + 3) * 16 + n] = v.w;
        }
    }
    const int tn  = tid >> 5;
    const int tb  = tid & 31;
    const int toff = (n0 + tn) * B_ + tb;
    __syncthreads();

    for (int t = 0; t < T_; t++) {
        const float* hin  = (t & 1) ? hB : hA;
        float*       hout = (t & 1) ? hA : hB;
        float*       Ut   = UT + (size_t)t * (RES_ * B_);
        const unsigned target = epoch + (unsigned)t;   // h(t-1) published level

        ull acc2[8];
#pragma unroll
        for (int j = 0; j < 8; j++) acc2[j] = 0ull;

        const float* hp = hin + (size_t)k0 * B_ + lane;

        // ---- ping-pong over 16 batches of 8 k, flag-gated per 16-row chunk ----
        float va[8], vb[8];
        wait_flag(&g_flags[cbase], target);            // chunk 0 of this warp
#pragma unroll
        for (int u = 0; u < 8; u++) va[u] = __ldcg(hp + u * B_);

#pragma unroll
        for (int kb = 0; kb < 128; kb += 16) {
            // second half of current chunk (same producer, already gated)
#pragma unroll
            for (int u = 0; u < 8; u++) vb[u] = __ldcg(hp + (kb + 8 + u) * B_);
            fma_block8(acc2, wS, k0 + kb, va);
            if (kb + 16 < 128) {
                wait_flag(&g_flags[cbase + (kb >> 4) + 1], target);  // next chunk
#pragma unroll
                for (int u = 0; u < 8; u++) va[u] = __ldcg(hp + (kb + 16 + u) * B_);
            }
            fma_block8(acc2, wS, k0 + kb + 8, vb);
        }

        // tail operand prefetch (overlaps reduction)
        float u_pref = __ldcg(Ut + toff);
        float hprev  = __ldcg(hin + toff);

        // cross-warp reduction
#pragma unroll
        for (int j = 0; j < 8; j++) {
            float lo, hi;
            unpack2(acc2[j], lo, hi);
            red[((2 * j + 0) * 16 + w) * 32 + lane] = lo;
            red[((2 * j + 1) * 16 + w) * 32 + lane] = hi;
        }
        __syncthreads();

        {
            float s = 0.f;
#pragma unroll
            for (int ww = 0; ww < 16; ww++) s += red[(tn * 16 + ww) * 32 + tb];
            float hn = 0.5f * hprev + 0.5f * tanhf(s + u_pref);
            __stcg(hout + toff, hn);
            __stcg(Ut + toff, hn);
        }
        __syncthreads();                     // all tail stores done + red reusable
        if (tid == 0) st_rel(&g_flags[bid], target + 1u);   // publish h(t)
    }
}

// ---------------- fused SGEMM-NT + bias + (GELU), f32x2 packed ----------------
__device__ __forceinline__ float gelu_f(float v)
{
    return 0.5f * v * (1.0f + erff(v * 0.70710678118654752f));
}

template <int A_MODE, int ACT, int OUT_MODE>
__global__ void __launch_bounds__(256) gemm_kernel(const float* __restrict__ A, int K,
                                                   const float* __restrict__ W,
                                                   const float* __restrict__ bias,
                                                   float* __restrict__ C, int ldc)
{
    __shared__ float As[16][132];
    __shared__ float Ws[16][64];
    const int m0  = blockIdx.x * 128;
    const int n0  = blockIdx.y * 64;
    const int tid = threadIdx.x;
    const int tx  = tid & 15;
    const int ty  = tid >> 4;

    ull c2[4][4];
#pragma unroll
    for (int i = 0; i < 4; i++)
#pragma unroll
        for (int j = 0; j < 4; j++) c2[i][j] = 0ull;

    for (int k0 = 0; k0 < K; k0 += 16) {
        if (A_MODE == 0) {
            int base = tid * 8;
            int b    = base & 31;
            int kk   = (base >> 5) & 15;
            int tt   = base >> 9;
            const float* src = A + ((size_t)(m0 >> 5) + tt) * (RES_ * B_) +
                               (size_t)(k0 + kk) * B_ + b;
            float4 v0 = *(const float4*)src;
            float4 v1 = *(const float4*)(src + 4);
            int mm = tt * 32 + b;
            *(float4*)&As[kk][mm]     = v0;
            *(float4*)&As[kk][mm + 4] = v1;
        } else {
            int mm = tid >> 1, kk = (tid & 1) * 8;
            const float* src = A + (size_t)(m0 + mm) * K + k0 + kk;
            float4 v0 = *(const float4*)src;
            float4 v1 = *(const float4*)(src + 4);
            As[kk + 0][mm] = v0.x; As[kk + 1][mm] = v0.y;
            As[kk + 2][mm] = v0.z; As[kk + 3][mm] = v0.w;
            As[kk + 4][mm] = v1.x; As[kk + 5][mm] = v1.y;
            As[kk + 6][mm] = v1.z; As[kk + 7][mm] = v1.w;
        }
        {
            int n = tid >> 2, kq = (tid & 3) * 4;
            const float* src = W + (size_t)(n0 + n) * K + k0 + kq;
            float4 v = *(const float4*)src;
            Ws[kq + 0][n] = v.x; Ws[kq + 1][n] = v.y;
            Ws[kq + 2][n] = v.z; Ws[kq + 3][n] = v.w;
        }
        __syncthreads();
#pragma unroll
        for (int kk = 0; kk < 16; kk++) {
            ulonglong2 a01 = *(const ulonglong2*)&As[kk][ty * 8];
            ulonglong2 a23 = *(const ulonglong2*)&As[kk][ty * 8 + 4];
            float4 wv = *(const float4*)&Ws[kk][tx * 4];
            ull w0 = splat2(wv.x), w1 = splat2(wv.y), w2 = splat2(wv.z), w3 = splat2(wv.w);
            ffma2(c2[0][0], a01.x, w0); ffma2(c2[0][1], a01.x, w1);
            ffma2(c2[0][2], a01.x, w2); ffma2(c2[0][3], a01.x, w3);
            ffma2(c2[1][0], a01.y, w0); ffma2(c2[1][1], a01.y, w1);
            ffma2(c2[1][2], a01.y, w2); ffma2(c2[1][3], a01.y, w3);
            ffma2(c2[2][0], a23.x, w0); ffma2(c2[2][1], a23.x, w1);
            ffma2(c2[2][2], a23.x, w2); ffma2(c2[2][3], a23.x, w3);
            ffma2(c2[3][0], a23.y, w0); ffma2(c2[3][1], a23.y, w1);
            ffma2(c2[3][2], a23.y, w2); ffma2(c2[3][3], a23.y, w3);
        }
        __syncthreads();
    }

    float bv[4];
#pragma unroll
    for (int j = 0; j < 4; j++) bv[j] = bias[n0 + tx * 4 + j];

#pragma unroll
    for (int ip = 0; ip < 4; ip++) {
#pragma unroll
        for (int half = 0; half < 2; half++) {
            float r[4];
#pragma unroll
            for (int j = 0; j < 4; j++) {
                float lo, hi;
                unpack2(c2[ip][j], lo, hi);
                float v = (half == 0 ? lo : hi) + bv[j];
                r[j] = (ACT == 1) ? gelu_f(v) : v;
            }
            float4 v4 = make_float4(r[0], r[1], r[2], r[3]);
            int m = m0 + ty * 8 + ip * 2 + half;
            if (OUT_MODE == 0) {
                *(float4*)(C + (size_t)m * ldc + n0 + tx * 4) = v4;
            } else {
                int t = m >> 5, b = m & 31;
                *(float4*)(C + (size_t)b * (T_ * OUT_) + (size_t)t * OUT_ + tx * 4) = v4;
            }
        }
    }
}

// ---------------- h_n: transpose hsT[1023][r][b] -> out[b][r] ----------------
__global__ void hn_kernel(const float* __restrict__ hT, float* __restrict__ out)
{
    int i = blockIdx.x * 256 + threadIdx.x;
    int r = i >> 5, b = i & 31;
    out[(size_t)b * RES_ + r] = hT[i];
}

// ---------------- launch ----------------
extern "C" void kernel_launch(void* const* d_in, const int* in_sizes, int n_in,
                              void* d_out, int out_size)
{
    const float* x    = (const float*)d_in[0];
    const float* Win  = (const float*)d_in[1];
    const float* Wh   = (const float*)d_in[2];
    const float* W0   = (const float*)d_in[3];
    const float* b0   = (const float*)d_in[4];
    const float* W1   = (const float*)d_in[5];
    const float* b1   = (const float*)d_in[6];
    const float* W2   = (const float*)d_in[7];
    const float* b2   = (const float*)d_in[8];
    float*       out  = (float*)d_out;

    float *UT, *h0, *h1, *a1, *a2;
    cudaGetSymbolAddress((void**)&UT, g_UT);
    cudaGetSymbolAddress((void**)&h0, g_h0);
    cudaGetSymbolAddress((void**)&h1, g_h1);
    cudaGetSymbolAddress((void**)&a1, g_a1);
    cudaGetSymbolAddress((void**)&a2, g_a2);

    const int SCAN_SMEM = (RES_ * 16 + 16 * 16 * 32) * (int)sizeof(float);  // 160 KB
    cudaFuncSetAttribute(scan_persistent_kernel,
                         cudaFuncAttributeMaxDynamicSharedMemorySize, SCAN_SMEM);

    u_kernel<<<dim3(16, 1024), 256>>>(x, Win, UT);
    cudaMemsetAsync(h0, 0, (size_t)RES_ * B_ * sizeof(float));

    scan_persistent_kernel<<<NCTA_, 512, SCAN_SMEM>>>(Wh, h0, h1, UT);

    gemm_kernel<0, 1, 0><<<dim3(BT_ / 128, HID_ / 64), 256>>>(UT, RES_, W0, b0, a1, HID_);
    gemm_kernel<1, 1, 0><<<dim3(BT_ / 128, HID_ / 64), 256>>>(a1, HID_, W1, b1, a2, HID_);
    gemm_kernel<1, 0, 1><<<dim3(BT_ / 128, 1), 256>>>(a2, HID_, W2, b2, out, OUT_);

    if (out_size >= (int)((size_t)B_ * T_ * OUT_ + (size_t)B_ * RES_)) {
        hn_kernel<<<RES_ * B_ / 256, 256>>>(UT + (size_t)(T_ - 1) * (RES_ * B_),
                                            out + (size_t)B_ * T_ * OUT_);
    }
}

// round 7
// speedup vs baseline: 1.2975x; 1.2975x over previous
#include <cuda_runtime.h>
#include <math.h>

#define B_   32
#define T_   1024
#define IN_  64
#define RES_ 2048
#define HID_ 512
#define OUT_ 64
#define BT_  (B_ * T_)
#define NCTA_ 128

typedef unsigned long long ull;

// ---- packed fp32x2 helpers ----
__device__ __forceinline__ void ffma2(ull& d, ull a, ull b)
{
    asm("fma.rn.f32x2 %0, %1, %2, %0;" : "+l"(d) : "l"(a), "l"(b));
}
__device__ __forceinline__ ull splat2(float h)
{
    ull r;
    asm("mov.b64 %0, {%1, %1};" : "=l"(r) : "f"(h));
    return r;
}
__device__ __forceinline__ void unpack2(ull v, float& lo, float& hi)
{
    asm("mov.b64 {%0, %1}, %2;" : "=f"(lo), "=f"(hi) : "l"(v));
}

// ---- acq/rel sync primitives (no membar -> no CCTL.IVALL L1 flush) ----
__device__ __forceinline__ unsigned ld_acq(const unsigned* p)
{
    unsigned v;
    asm volatile("ld.acquire.gpu.global.u32 %0, [%1];" : "=r"(v) : "l"(p));
    return v;
}
__device__ __forceinline__ void st_rel(unsigned* p, unsigned v)
{
    asm volatile("st.release.gpu.global.u32 [%0], %1;" :: "l"(p), "r"(v) : "memory");
}
__device__ __forceinline__ unsigned atom_add_acqrel(unsigned* p, unsigned v)
{
    unsigned old;
    asm volatile("atom.add.acq_rel.gpu.global.u32 %0, [%1], %2;"
                 : "=r"(old) : "l"(p), "r"(v) : "memory");
    return old;
}

// ---------------- scratch ----------------
__device__ float g_UT[(size_t)T_ * RES_ * B_];
__device__ float g_h0[RES_ * B_];
__device__ float g_h1[RES_ * B_];
__device__ float g_a1[(size_t)BT_ * HID_];
__device__ float g_a2[(size_t)BT_ * HID_];
// tree-barrier state: [l*32] leaf counters (l=0..7), [256] root, [288] gen.
// memset to 0 by a graph node before every scan launch.
__device__ unsigned g_bar[512];

// ---------------- U = x @ W_in^T -> UT[t][r][b] ----------------
__global__ void __launch_bounds__(256) u_kernel(const float* __restrict__ x,
                                                const float* __restrict__ Win,
                                                float* __restrict__ UT)
{
    __shared__ float xS[IN_][B_];
    __shared__ float wS[IN_][128];
    const int t   = blockIdx.y;
    const int R0  = blockIdx.x * 128;
    const int tid = threadIdx.x;

    {
        int b  = tid >> 3;
        int iq = (tid & 7) * 8;
        const float* src = x + (size_t)b * (T_ * IN_) + (size_t)t * IN_ + iq;
        float4 v0 = *(const float4*)(src);
        float4 v1 = *(const float4*)(src + 4);
        xS[iq + 0][b] = v0.x; xS[iq + 1][b] = v0.y; xS[iq + 2][b] = v0.z; xS[iq + 3][b] = v0.w;
        xS[iq + 4][b] = v1.x; xS[iq + 5][b] = v1.y; xS[iq + 6][b] = v1.z; xS[iq + 7][b] = v1.w;
    }
    {
        int r  = tid >> 1;
        int ih = (tid & 1) * 32;
        const float* src = Win + (size_t)(R0 + r) * IN_ + ih;
#pragma unroll
        for (int j = 0; j < 32; j += 4) {
            float4 v = *(const float4*)(src + j);
            wS[ih + j + 0][r] = v.x; wS[ih + j + 1][r] = v.y;
            wS[ih + j + 2][r] = v.z; wS[ih + j + 3][r] = v.w;
        }
    }
    __syncthreads();

    const int tx = tid & 7, ty = tid >> 3;
    const int b0 = tx * 4, r0 = ty * 4;
    float acc[4][4];
#pragma unroll
    for (int i = 0; i < 4; i++)
#pragma unroll
        for (int j = 0; j < 4; j++) acc[i][j] = 0.f;

#pragma unroll
    for (int i = 0; i < IN_; i++) {
        float4 xv = *(const float4*)&xS[i][b0];
        float4 wv = *(const float4*)&wS[i][r0];
        float xa[4] = {xv.x, xv.y, xv.z, xv.w};
        float wa[4] = {wv.x, wv.y, wv.z, wv.w};
#pragma unroll
        for (int ri = 0; ri < 4; ri++)
#pragma unroll
            for (int bi = 0; bi < 4; bi++)
                acc[ri][bi] = fmaf(wa[ri], xa[bi], acc[ri][bi]);
    }
    float* dst = UT + (size_t)t * (RES_ * B_);
#pragma unroll
    for (int ri = 0; ri < 4; ri++) {
        float4 v = make_float4(acc[ri][0], acc[ri][1], acc[ri][2], acc[ri][3]);
        *(float4*)(dst + (size_t)(R0 + r0 + ri) * B_ + b0) = v;
    }
}

// ---- 8-k FMA block ----
__device__ __forceinline__ void fma_block8(ull acc2[8], const float* __restrict__ wS,
                                           int kbase, const float hv[8])
{
#pragma unroll
    for (int u = 0; u < 8; u++) {
        const ull* wr = (const ull*)&wS[(kbase + u) * 16];
        ulonglong2 p0 = *(const ulonglong2*)(wr + 0);
        ulonglong2 p1 = *(const ulonglong2*)(wr + 2);
        ulonglong2 p2 = *(const ulonglong2*)(wr + 4);
        ulonglong2 p3 = *(const ulonglong2*)(wr + 6);
        ull hh = splat2(hv[u]);
        ffma2(acc2[0], p0.x, hh);
        ffma2(acc2[1], p0.y, hh);
        ffma2(acc2[2], p1.x, hh);
        ffma2(acc2[3], p1.y, hh);
        ffma2(acc2[4], p2.x, hh);
        ffma2(acc2[5], p2.y, hh);
        ffma2(acc2[6], p3.x, hh);
        ffma2(acc2[7], p3.y, hh);
    }
}

// ---------------- persistent ESN scan: R5 pipeline + membar-free tree barrier ----------------
__global__ void __launch_bounds__(512) scan_persistent_kernel(const float* __restrict__ Wh,
                                                              float* __restrict__ hA,
                                                              float* __restrict__ hB,
                                                              float* __restrict__ UT)
{
    extern __shared__ float dyn[];
    float* wS  = dyn;                 // wS[k*16 + n]
    float* red = dyn + RES_ * 16;     // red[(n*16 + w)*32 + b]

    const int tid  = threadIdx.x;
    const int w    = tid >> 5;
    const int lane = tid & 31;
    const int bid  = blockIdx.x;
    const int n0   = bid * 16;
    const int k0   = w * 128;
    const int leaf = bid >> 4;        // 8 leaves x 16 CTAs

    // one-time: cache W_hat slice transposed into SMEM
    {
        int n = tid >> 5;
        const float* row = Wh + (size_t)(n0 + n) * RES_;
#pragma unroll
        for (int j = 0; j < 16; j++) {
            int k = j * 128 + lane * 4;
            float4 v = *(const float4*)(row + k);
            wS[(k + 0) * 16 + n] = v.x;
            wS[(k + 1) * 16 + n] = v.y;
            wS[(k + 2) * 16 + n] = v.z;
            wS[(k + 3) * 16 + n] = v.w;
        }
    }
    const int tn   = tid >> 5;
    const int tb   = tid & 31;
    const int toff = (n0 + tn) * B_ + tb;
    __syncthreads();

    for (int t = 0; t < T_; t++) {
        const float* hin  = (t & 1) ? hB : hA;
        float*       hout = (t & 1) ? hA : hB;
        float*       Ut   = UT + (size_t)t * (RES_ * B_);

        ull acc2[8];
#pragma unroll
        for (int j = 0; j < 8; j++) acc2[j] = 0ull;

        const float* hp = hin + (size_t)k0 * B_ + lane;

        // ---- ping-pong prefetch over 16 batches of 8 k (no sync inside!) ----
        float va[8], vb[8];
#pragma unroll
        for (int u = 0; u < 8; u++) va[u] = __ldcg(hp + u * B_);

#pragma unroll
        for (int kb = 0; kb < 128; kb += 16) {
#pragma unroll
            for (int u = 0; u < 8; u++) vb[u] = __ldcg(hp + (kb + 8 + u) * B_);
            fma_block8(acc2, wS, k0 + kb, va);
            if (kb + 16 < 128) {
#pragma unroll
                for (int u = 0; u < 8; u++) va[u] = __ldcg(hp + (kb + 16 + u) * B_);
            }
            fma_block8(acc2, wS, k0 + kb + 8, vb);
        }

        // tail operand prefetch (overlaps reduction)
        float u_pref = __ldcg(Ut + toff);
        float hprev  = __ldcg(hin + toff);

        // cross-warp reduction
#pragma unroll
        for (int j = 0; j < 8; j++) {
            float lo, hi;
            unpack2(acc2[j], lo, hi);
            red[((2 * j + 0) * 16 + w) * 32 + lane] = lo;
            red[((2 * j + 1) * 16 + w) * 32 + lane] = hi;
        }
        __syncthreads();

        {
            float s = 0.f;
#pragma unroll
            for (int ww = 0; ww < 16; ww++) s += red[(tn * 16 + ww) * 32 + tb];
            float hn = 0.5f * hprev + 0.5f * tanhf(s + u_pref);
            __stcg(hout + toff, hn);
            __stcg(Ut + toff, hn);
        }

        // ---- membar-free tree barrier (ONE sync point, tid 0 only) ----
        if (t + 1 < T_) {
            __syncthreads();   // all stcg issued; bar gives cumulativity for tid0's release
            if (tid == 0) {
                unsigned lt = atom_add_acqrel(&g_bar[leaf * 32], 1u);
                if (lt == (unsigned)(16 * t + 15)) {              // last in leaf
                    unsigned rt = atom_add_acqrel(&g_bar[256], 1u);
                    if (rt == (unsigned)(8 * t + 7))              // last leaf
                        st_rel(&g_bar[288], (unsigned)(t + 1));
                }
                unsigned target = (unsigned)(t + 1);
                while ((int)(ld_acq(&g_bar[288]) - target) < 0) __nanosleep(32);
            }
            __syncthreads();   // fan acquire out to all warps; red reusable
        }
    }
}

// ---------------- fused SGEMM-NT + bias + (GELU), f32x2, double-buffered ----------------
__device__ __forceinline__ float gelu_f(float v)
{
    return 0.5f * v * (1.0f + erff(v * 0.70710678118654752f));
}

template <int A_MODE, int ACT, int OUT_MODE>
__global__ void __launch_bounds__(256) gemm_kernel(const float* __restrict__ A, int K,
                                                   const float* __restrict__ W,
                                                   const float* __restrict__ bias,
                                                   float* __restrict__ C, int ldc)
{
    __shared__ float As[2][16][132];
    __shared__ float Ws[2][16][64];
    const int m0  = blockIdx.x * 128;
    const int n0  = blockIdx.y * 64;
    const int tid = threadIdx.x;
    const int tx  = tid & 15;
    const int ty  = tid >> 4;

    // per-thread load indices (fixed across tiles)
    int la_b = 0, la_kk = 0, la_tt = 0, la_mm = 0;
    if (A_MODE == 0) {
        int base = tid * 8;
        la_b  = base & 31;
        la_kk = (base >> 5) & 15;
        la_tt = base >> 9;
        la_mm = la_tt * 32 + la_b;
    } else {
        la_mm = tid >> 1;
        la_kk = (tid & 1) * 8;
    }
    const int lw_n  = tid >> 2;
    const int lw_kq = (tid & 3) * 4;

    float a_ld[8];
    float w_ld[4];

    // ---- tile loaders ----
    auto ldg_tile = [&](int k0) {
        if (A_MODE == 0) {
            const float* src = A + ((size_t)(m0 >> 5) + la_tt) * (RES_ * B_) +
                               (size_t)(k0 + la_kk) * B_ + la_b;
            float4 v0 = *(const float4*)src;
            float4 v1 = *(const float4*)(src + 4);
            a_ld[0] = v0.x; a_ld[1] = v0.y; a_ld[2] = v0.z; a_ld[3] = v0.w;
            a_ld[4] = v1.x; a_ld[5] = v1.y; a_ld[6] = v1.z; a_ld[7] = v1.w;
        } else {
            const float* src = A + (size_t)(m0 + la_mm) * K + k0 + la_kk;
            float4 v0 = *(const float4*)src;
            float4 v1 = *(const float4*)(src + 4);
            a_ld[0] = v0.x; a_ld[1] = v0.y; a_ld[2] = v0.z; a_ld[3] = v0.w;
            a_ld[4] = v1.x; a_ld[5] = v1.y; a_ld[6] = v1.z; a_ld[7] = v1.w;
        }
        const float* srw = W + (size_t)(n0 + lw_n) * K + k0 + lw_kq;
        float4 v = *(const float4*)srw;
        w_ld[0] = v.x; w_ld[1] = v.y; w_ld[2] = v.z; w_ld[3] = v.w;
    };
    auto sts_tile = [&](int buf) {
        if (A_MODE == 0) {
            *(float4*)&As[buf][la_kk][la_mm]     = make_float4(a_ld[0], a_ld[1], a_ld[2], a_ld[3]);
            *(float4*)&As[buf][la_kk][la_mm + 4] = make_float4(a_ld[4], a_ld[5], a_ld[6], a_ld[7]);
        } else {
#pragma unroll
            for (int j = 0; j < 8; j++) As[buf][la_kk + j][la_mm] = a_ld[j];
        }
#pragma unroll
        for (int j = 0; j < 4; j++) Ws[buf][lw_kq + j][lw_n] = w_ld[j];
    };

    ull c2[4][4];
#pragma unroll
    for (int i = 0; i < 4; i++)
#pragma unroll
        for (int j = 0; j < 4; j++) c2[i][j] = 0ull;

    // prologue
    ldg_tile(0);
    sts_tile(0);
    __syncthreads();

    for (int k0 = 0; k0 < K; k0 += 16) {
        const int cur = (k0 >> 4) & 1;
        const bool more = (k0 + 16 < K);
        if (more) ldg_tile(k0 + 16);          // LDG overlaps compute below

#pragma unroll
        for (int kk = 0; kk < 16; kk++) {
            ulonglong2 a01 = *(const ulonglong2*)&As[cur][kk][ty * 8];
            ulonglong2 a23 = *(const ulonglong2*)&As[cur][kk][ty * 8 + 4];
            float4 wv = *(const float4*)&Ws[cur][kk][tx * 4];
            ull w0 = splat2(wv.x), w1 = splat2(wv.y), w2 = splat2(wv.z), w3 = splat2(wv.w);
            ffma2(c2[0][0], a01.x, w0); ffma2(c2[0][1], a01.x, w1);
            ffma2(c2[0][2], a01.x, w2); ffma2(c2[0][3], a01.x, w3);
            ffma2(c2[1][0], a01.y, w0); ffma2(c2[1][1], a01.y, w1);
            ffma2(c2[1][2], a01.y, w2); ffma2(c2[1][3], a01.y, w3);
            ffma2(c2[2][0], a23.x, w0); ffma2(c2[2][1], a23.x, w1);
            ffma2(c2[2][2], a23.x, w2); ffma2(c2[2][3], a23.x, w3);
            ffma2(c2[3][0], a23.y, w0); ffma2(c2[3][1], a23.y, w1);
            ffma2(c2[3][2], a23.y, w2); ffma2(c2[3][3], a23.y, w3);
        }

        if (more) {
            sts_tile(cur ^ 1);
            __syncthreads();
        }
    }

    float bv[4];
#pragma unroll
    for (int j = 0; j < 4; j++) bv[j] = bias[n0 + tx * 4 + j];

#pragma unroll
    for (int ip = 0; ip < 4; ip++) {
#pragma unroll
        for (int half = 0; half < 2; half++) {
            float r[4];
#pragma unroll
            for (int j = 0; j < 4; j++) {
                float lo, hi;
                unpack2(c2[ip][j], lo, hi);
                float v = (half == 0 ? lo : hi) + bv[j];
                r[j] = (ACT == 1) ? gelu_f(v) : v;
            }
            float4 v4 = make_float4(r[0], r[1], r[2], r[3]);
            int m = m0 + ty * 8 + ip * 2 + half;
            if (OUT_MODE == 0) {
                *(float4*)(C + (size_t)m * ldc + n0 + tx * 4) = v4;
            } else {
                int t = m >> 5, b = m & 31;
                *(float4*)(C + (size_t)b * (T_ * OUT_) + (size_t)t * OUT_ + tx * 4) = v4;
            }
        }
    }
}

// ---------------- h_n: transpose hsT[1023][r][b] -> out[b][r] ----------------
__global__ void hn_kernel(const float* __restrict__ hT, float* __restrict__ out)
{
    int i = blockIdx.x * 256 + threadIdx.x;
    int r = i >> 5, b = i & 31;
    out[(size_t)b * RES_ + r] = hT[i];
}

// ---------------- launch ----------------
extern "C" void kernel_launch(void* const* d_in, const int* in_sizes, int n_in,
                              void* d_out, int out_size)
{
    const float* x    = (const float*)d_in[0];
    const float* Win  = (const float*)d_in[1];
    const float* Wh   = (const float*)d_in[2];
    const float* W0   = (const float*)d_in[3];
    const float* b0   = (const float*)d_in[4];
    const float* W1   = (const float*)d_in[5];
    const float* b1   = (const float*)d_in[6];
    const float* W2   = (const float*)d_in[7];
    const float* b2   = (const float*)d_in[8];
    float*       out  = (float*)d_out;

    float *UT, *h0, *h1, *a1, *a2;
    unsigned* bar;
    cudaGetSymbolAddress((void**)&UT, g_UT);
    cudaGetSymbolAddress((void**)&h0, g_h0);
    cudaGetSymbolAddress((void**)&h1, g_h1);
    cudaGetSymbolAddress((void**)&a1, g_a1);
    cudaGetSymbolAddress((void**)&a2, g_a2);
    cudaGetSymbolAddress((void**)&bar, g_bar);

    const int SCAN_SMEM = (RES_ * 16 + 16 * 16 * 32) * (int)sizeof(float);  // 160 KB
    cudaFuncSetAttribute(scan_persistent_kernel,
                         cudaFuncAttributeMaxDynamicSharedMemorySize, SCAN_SMEM);

    u_kernel<<<dim3(16, 1024), 256>>>(x, Win, UT);
    cudaMemsetAsync(h0, 0, (size_t)RES_ * B_ * sizeof(float));
    cudaMemsetAsync(bar, 0, 512 * sizeof(unsigned));   // reset barrier state every replay

    scan_persistent_kernel<<<NCTA_, 512, SCAN_SMEM>>>(Wh, h0, h1, UT);

    gemm_kernel<0, 1, 0><<<dim3(BT_ / 128, HID_ / 64), 256>>>(UT, RES_, W0, b0, a1, HID_);
    gemm_kernel<1, 1, 0><<<dim3(BT_ / 128, HID_ / 64), 256>>>(a1, HID_, W1, b1, a2, HID_);
    gemm_kernel<1, 0, 1><<<dim3(BT_ / 128, 1), 256>>>(a2, HID_, W2, b2, out, OUT_);

    if (out_size >= (int)((size_t)B_ * T_ * OUT_ + (size_t)B_ * RES_)) {
        hn_kernel<<<RES_ * B_ / 256, 256>>>(UT + (size_t)(T_ - 1) * (RES_ * B_),
                                            out + (size_t)B_ * T_ * OUT_);
    }
}